// round 1
// baseline (speedup 1.0000x reference)
#include <cuda_runtime.h>
#include <cuda_bf16.h>
#include <cstdint>

// Problem constants
#define BS   32
#define N    1024
#define FOUT 128

// Scratch (device globals: allocation-free rule)
__device__ float  g_c[2];                 // c1 = W·a1, c2 = W·a2
__device__ float  g_meanx[BS];            // per-batch mean of x
__device__ float2 g_P[BS * N];            // swizzled (x, exp(c2*x)) per (b,j)
__device__ unsigned g_bits[N * (N / 32)]; // adjacency bitmask, row-major words

// ---------------------------------------------------------------------------
// Kernel A: c1 = sum_f W[f]*a[f], c2 = sum_f W[f]*a[128+f]
// ---------------------------------------------------------------------------
__global__ void k_coef(const float* __restrict__ W, const float* __restrict__ a) {
    __shared__ float s1[FOUT], s2[FOUT];
    int t = threadIdx.x;          // 128 threads
    float w = W[t];
    s1[t] = w * a[t];
    s2[t] = w * a[FOUT + t];
    __syncthreads();
    for (int off = 64; off > 0; off >>= 1) {
        if (t < off) { s1[t] += s1[t + off]; s2[t] += s2[t + off]; }
        __syncthreads();
    }
    if (t == 0) { g_c[0] = s1[0]; g_c[1] = s2[0]; }
}

// ---------------------------------------------------------------------------
// Kernel B: per (b,j) pack (x, exp(c2*x)) swizzled so that the main kernel's
// lane l / iter k access (k*32+l) is conflict-free; also per-batch mean.
// Swizzle: logical j stored at ((j&31)<<5) | (j>>5).
// ---------------------------------------------------------------------------
__global__ void k_prep(const float* __restrict__ input) {
    int b = blockIdx.x;           // 32 blocks
    int j = threadIdx.x;          // 1024 threads
    float c2 = g_c[1];
    float x = input[b * N + j];
    float e2 = expf(c2 * x);
    g_P[b * N + (((j & 31) << 5) | (j >> 5))] = make_float2(x, e2);

    __shared__ float red[N];
    red[j] = x;
    __syncthreads();
    for (int off = 512; off > 0; off >>= 1) {
        if (j < off) red[j] += red[j + off];
        __syncthreads();
    }
    if (j == 0) g_meanx[b] = red[0] * (1.0f / (float)N);
}

// ---------------------------------------------------------------------------
// Kernel C: pack adj (0/1 int32) into bitmask words via warp ballot.
// ---------------------------------------------------------------------------
__global__ void k_bits(const int* __restrict__ adj) {
    int i = blockIdx.x;           // 1024 blocks
    int w = threadIdx.x >> 5;     // 8 warps
    int l = threadIdx.x & 31;
    const int* row = adj + (size_t)i * N;
    for (int ww = w; ww < 32; ww += 8) {
        int v = row[ww * 32 + l];
        unsigned m = __ballot_sync(0xffffffffu, v > 0);
        if (l == 0) g_bits[i * 32 + ww] = m;
    }
}

// ---------------------------------------------------------------------------
// Main kernel: one warp per output row (b, i).
// Block = 512 threads (16 warps) covering 16 rows of one batch.
// Grid = BS * (N/16) = 2048.
// y[b,i] = sum_{valid j} e2_j * x_j / sum_{valid j} e2_j,
// valid = adj-bit & (c1*xi + c2*xj > 0); empty-valid -> y = mean(x[b,:]).
// out[b,i,f] = elu(y * W[f]).
// ---------------------------------------------------------------------------
__device__ __forceinline__ float elu1(float z) {
    return z > 0.0f ? z : expm1f(z);
}

__global__ void __launch_bounds__(512, 2) k_main(const float* __restrict__ W,
                                                 float* __restrict__ out) {
    int b     = blockIdx.x >> 6;       // 64 i-tiles per batch
    int itile = blockIdx.x & 63;
    int warp  = threadIdx.x >> 5;
    int lane  = threadIdx.x & 31;
    int i     = itile * 16 + warp;

    __shared__ float2 Ps[N];                 // 8 KB: (x, e2) swizzled, batch b
    __shared__ __align__(16) float Ws[FOUT]; // 512 B

    const float2* Pg = g_P + b * N;
    for (int t = threadIdx.x; t < N; t += 512) Ps[t] = Pg[t];
    if (threadIdx.x < FOUT) Ws[threadIdx.x] = W[threadIdx.x];
    __syncthreads();

    float c1 = g_c[0];
    float c2 = g_c[1];
    // x[b,i] lives at swizzled slot ((i&31)<<5)|(i>>5)
    float xi = Ps[((i & 31) << 5) | (i >> 5)].x;
    float t0 = c1 * xi;

    // lane l owns logical j = l*32 + k for k=0..31 -> bitmask word = bits[i*32+l], bit k
    unsigned wbits = g_bits[i * 32 + lane];

    float sumE = 0.0f, sumEx = 0.0f;
    int cnt = 0;
#pragma unroll
    for (int k = 0; k < 32; k++) {
        float2 p = Ps[k * 32 + lane];        // conflict-free (2-phase LDS.64)
        float s = fmaf(c2, p.x, t0);
        bool pr = ((wbits >> k) & 1u) && (s > 0.0f);
        if (pr) {
            sumE += p.y;
            sumEx = fmaf(p.y, p.x, sumEx);
            cnt++;
        }
    }
#pragma unroll
    for (int off = 16; off > 0; off >>= 1) {
        sumE  += __shfl_xor_sync(0xffffffffu, sumE,  off);
        sumEx += __shfl_xor_sync(0xffffffffu, sumEx, off);
        cnt   += __shfl_xor_sync(0xffffffffu, cnt,   off);
    }

    float y = (cnt > 0) ? (sumEx / sumE) : g_meanx[b];

    int f0 = lane * 4;
    float4 wv = *reinterpret_cast<const float4*>(&Ws[f0]);
    float4 o;
    o.x = elu1(y * wv.x);
    o.y = elu1(y * wv.y);
    o.z = elu1(y * wv.z);
    o.w = elu1(y * wv.w);
    size_t base = ((size_t)(b * N + i)) * FOUT + f0;
    *reinterpret_cast<float4*>(out + base) = o;
}

// ---------------------------------------------------------------------------
// Launch: inputs (metadata order): input, adj, ext_input, side_input, W, a
// ---------------------------------------------------------------------------
extern "C" void kernel_launch(void* const* d_in, const int* in_sizes, int n_in,
                              void* d_out, int out_size) {
    const float* input = (const float*)d_in[0];
    const int*   adj   = (const int*)d_in[1];
    const float* W     = (const float*)d_in[4];
    const float* a     = (const float*)d_in[5];
    float* out = (float*)d_out;

    k_coef<<<1, 128>>>(W, a);
    k_prep<<<BS, N>>>(input);
    k_bits<<<N, 256>>>(adj);
    k_main<<<BS * (N / 16), 512>>>(W, out);
}

// round 8
// speedup vs baseline: 1.4457x; 1.4457x over previous
#include <cuda_runtime.h>
#include <cuda_bf16.h>
#include <cstdint>

#define BS   32
#define N    1024
#define FOUT 128
#define NHALF 512

// Device-global scratch (allocation-free rule)
__device__ float  g_c[2];                     // c1 = W·a1, c2 = W·a2
__device__ float  g_meanx[BS];                // per-batch mean of x
__device__ float2 g_P[N * BS];                // (x, exp(c2*x)) layout [j][b]
__device__ unsigned short g_nbr[2 * N * NHALF]; // [half][i][slot] local j (0..511)
__device__ int    g_deg[2 * N];               // [half][i]

// ---------------------------------------------------------------------------
// K1: fused prep. Blocks 0..31: per-batch (c, P-table, mean). Blocks 32..1055:
// per-row adjacency compaction into uint16 neighbor lists (deterministic order).
// ---------------------------------------------------------------------------
__global__ void __launch_bounds__(256) k_pre(const float* __restrict__ input,
                                             const int* __restrict__ adj,
                                             const float* __restrict__ W,
                                             const float* __restrict__ a) {
    int bid = blockIdx.x;
    int tid = threadIdx.x;
    int lane = tid & 31;
    int w = tid >> 5;

    if (bid < BS) {
        // ---- compute c1, c2 (redundantly per block; block 0 publishes) ----
        __shared__ float sred[16];
        float p1 = 0.f, p2 = 0.f;
        if (tid < FOUT) {
            float wv = W[tid];
            p1 = wv * a[tid];
            p2 = wv * a[FOUT + tid];
        }
#pragma unroll
        for (int o = 16; o; o >>= 1) {
            p1 += __shfl_xor_sync(0xffffffffu, p1, o);
            p2 += __shfl_xor_sync(0xffffffffu, p2, o);
        }
        if (lane == 0) { sred[w] = p1; sred[8 + w] = p2; }
        __syncthreads();
        float c2 = sred[8] + sred[9] + sred[10] + sred[11]
                 + sred[12] + sred[13] + sred[14] + sred[15];
        if (bid == 0 && tid == 0) {
            float c1 = sred[0] + sred[1] + sred[2] + sred[3]
                     + sred[4] + sred[5] + sred[6] + sred[7];
            g_c[0] = c1; g_c[1] = c2;
        }

        // ---- P table (transposed [j][b]) + per-batch mean ----
        int b = bid;
        float xs = 0.f;
#pragma unroll
        for (int g = 0; g < 4; g++) {
            int j = g * 256 + tid;
            float x = input[b * N + j];
            xs += x;
            g_P[j * BS + b] = make_float2(x, expf(c2 * x));
        }
#pragma unroll
        for (int o = 16; o; o >>= 1) xs += __shfl_xor_sync(0xffffffffu, xs, o);
        __shared__ float sm[8];
        if (lane == 0) sm[w] = xs;
        __syncthreads();
        if (tid == 0) {
            float t = 0.f;
#pragma unroll
            for (int k = 0; k < 8; k++) t += sm[k];
            g_meanx[b] = t * (1.0f / (float)N);
        }
    } else {
        // ---- neighbor compaction for row i ----
        int i = bid - BS;
        __shared__ int wbase[32];
        __shared__ int wcnt[32];
        const int* row = adj + (size_t)i * N;
        unsigned bal[4];
#pragma unroll
        for (int g = 0; g < 4; g++) {
            int j = g * 256 + tid;
            bal[g] = __ballot_sync(0xffffffffu, row[j] > 0);
        }
        if (lane == 0) {
#pragma unroll
            for (int g = 0; g < 4; g++) wcnt[g * 8 + w] = __popc(bal[g]);
        }
        __syncthreads();
        if (tid == 0) {
            int acc0 = 0, acc1 = 0;
            for (int o = 0; o < 32; o++) {
                if (o < 16) { wbase[o] = acc0; acc0 += wcnt[o]; }
                else        { wbase[o] = acc1; acc1 += wcnt[o]; }
            }
            g_deg[i] = acc0;       // half 0 (j in [0,512))
            g_deg[N + i] = acc1;   // half 1 (j in [512,1024))
        }
        __syncthreads();
#pragma unroll
        for (int g = 0; g < 4; g++) {
            int j = g * 256 + tid;
            int half = g >> 1;
            unsigned m = bal[g];
            int rank = __popc(m & ((1u << lane) - 1u));
            int base = wbase[g * 8 + w];
            if ((m >> lane) & 1u)
                g_nbr[half * (N * NHALF) + i * NHALF + base + rank] =
                    (unsigned short)(j & (NHALF - 1));
        }
    }
}

// ---------------------------------------------------------------------------
// K2: main. Block = 8 warps = 8 rows. Warp = row i, lane = batch b.
// 128KB dynamic smem holds one 512-j half of the P table, so every LDS.64
// indexes [idx*32 + lane] -> broadcast-free, conflict-free 2-phase access.
// ---------------------------------------------------------------------------
extern __shared__ float2 Ps[];   // NHALF * BS float2 = 128 KB

__device__ __forceinline__ float elu1(float z) {
    return z > 0.0f ? z : (__expf(z) - 1.0f);
}

__global__ void __launch_bounds__(256, 1) k_mainv2(const float* __restrict__ W,
                                                   float* __restrict__ out) {
    int tid  = threadIdx.x;
    int lane = tid & 31;
    int w    = tid >> 5;
    int i    = blockIdx.x * 8 + w;

    float c1 = g_c[0];
    float c2 = g_c[1];
    float t0 = c1 * g_P[i * BS + lane].x;     // s1 contribution for (b=lane, i)

    float sumE = 0.f, sumEx = 0.f;

    float4* Psv = reinterpret_cast<float4*>(Ps);
    const float4* Pg = reinterpret_cast<const float4*>(g_P);

#pragma unroll 1
    for (int half = 0; half < 2; half++) {
        // stage 512-j half: 8192 float4
        const float4* src = Pg + half * (NHALF * BS / 2);
#pragma unroll
        for (int t = tid; t < NHALF * BS / 2; t += 256) Psv[t] = src[t];
        __syncthreads();

        int deg = g_deg[half * N + i];
        const unsigned short* lst = g_nbr + half * (N * NHALF) + (size_t)i * NHALF;

        int t = 0;
        for (; t + 4 <= deg; t += 4) {
            ushort4 q = *reinterpret_cast<const ushort4*>(lst + t);
            float2 p0 = Ps[(int)q.x * BS + lane];
            float2 p1 = Ps[(int)q.y * BS + lane];
            float2 p2 = Ps[(int)q.z * BS + lane];
            float2 p3 = Ps[(int)q.w * BS + lane];
            float e0 = (fmaf(c2, p0.x, t0) > 0.f) ? p0.y : 0.f;
            float e1 = (fmaf(c2, p1.x, t0) > 0.f) ? p1.y : 0.f;
            float e2 = (fmaf(c2, p2.x, t0) > 0.f) ? p2.y : 0.f;
            float e3 = (fmaf(c2, p3.x, t0) > 0.f) ? p3.y : 0.f;
            sumE += e0; sumEx = fmaf(e0, p0.x, sumEx);
            sumE += e1; sumEx = fmaf(e1, p1.x, sumEx);
            sumE += e2; sumEx = fmaf(e2, p2.x, sumEx);
            sumE += e3; sumEx = fmaf(e3, p3.x, sumEx);
        }
        for (; t < deg; t++) {
            int idx = lst[t];
            float2 p = Ps[idx * BS + lane];
            float e = (fmaf(c2, p.x, t0) > 0.f) ? p.y : 0.f;
            sumE += e; sumEx = fmaf(e, p.x, sumEx);
        }
        __syncthreads();   // protect smem before next half's staging
    }

    // y for (b=lane, i); empty/filtered-out rows fall back to batch mean
    float y = (sumE > 0.f) ? (sumEx / sumE) : g_meanx[lane];

    // epilogue: broadcast each batch's y, write 128 outputs (float4/lane)
    float4 wv = *reinterpret_cast<const float4*>(W + lane * 4);
#pragma unroll 1
    for (int b = 0; b < BS; b++) {
        float yb = __shfl_sync(0xffffffffu, y, b);
        float4 o;
        o.x = elu1(yb * wv.x);
        o.y = elu1(yb * wv.y);
        o.z = elu1(yb * wv.z);
        o.w = elu1(yb * wv.w);
        size_t base = ((size_t)b * N + i) * FOUT + lane * 4;
        *reinterpret_cast<float4*>(out + base) = o;
    }
}

// ---------------------------------------------------------------------------
// Launch. Inputs (metadata order): input, adj, ext_input, side_input, W, a
// ---------------------------------------------------------------------------
extern "C" void kernel_launch(void* const* d_in, const int* in_sizes, int n_in,
                              void* d_out, int out_size) {
    const float* input = (const float*)d_in[0];
    const int*   adj   = (const int*)d_in[1];
    const float* W     = (const float*)d_in[4];
    const float* a     = (const float*)d_in[5];
    float* out = (float*)d_out;

    cudaFuncSetAttribute(k_mainv2, cudaFuncAttributeMaxDynamicSharedMemorySize,
                         NHALF * BS * (int)sizeof(float2));

    k_pre<<<BS + N, 256>>>(input, adj, W, a);
    k_mainv2<<<N / 8, 256, NHALF * BS * sizeof(float2)>>>(W, out);
}

// round 15
// speedup vs baseline: 1.9908x; 1.3771x over previous
#include <cuda_runtime.h>
#include <cuda_bf16.h>
#include <cstdint>

#define BS    32
#define N     1024
#define FOUT  128
#define NSEG  4
#define SEGJ  256          // j per segment

// Device-global scratch (allocation-free rule)
__device__ float  g_c[2];                      // c1 = W·a1, c2 = W·a2
__device__ float  g_meanx[BS];                 // per-batch mean of x
__device__ float2 g_P[N * BS];                 // (x, exp(c2*x)) layout [j][b]
__device__ unsigned short g_nbr[NSEG * N * SEGJ]; // [seg][i][slot] local j (0..255)
__device__ int    g_deg[NSEG * N];             // [seg][i]
__device__ float2 g_part[NSEG * N * BS];       // per-(seg,row,batch) partial (sumE,sumEx)

// ---------------------------------------------------------------------------
// K1: fused prep. Blocks 0..31: per-batch (c, P-table, mean). Blocks 32..1055:
// per-row adjacency compaction into per-segment uint16 neighbor lists.
// ---------------------------------------------------------------------------
__global__ void __launch_bounds__(256) k_pre(const float* __restrict__ input,
                                             const int* __restrict__ adj,
                                             const float* __restrict__ W,
                                             const float* __restrict__ a) {
    int bid = blockIdx.x;
    int tid = threadIdx.x;
    int lane = tid & 31;
    int w = tid >> 5;

    if (bid < BS) {
        // ---- c1, c2 (redundant per block; block 0 publishes) ----
        __shared__ float sred[16];
        float p1 = 0.f, p2 = 0.f;
        if (tid < FOUT) {
            float wv = W[tid];
            p1 = wv * a[tid];
            p2 = wv * a[FOUT + tid];
        }
#pragma unroll
        for (int o = 16; o; o >>= 1) {
            p1 += __shfl_xor_sync(0xffffffffu, p1, o);
            p2 += __shfl_xor_sync(0xffffffffu, p2, o);
        }
        if (lane == 0) { sred[w] = p1; sred[8 + w] = p2; }
        __syncthreads();
        float c2 = sred[8] + sred[9] + sred[10] + sred[11]
                 + sred[12] + sred[13] + sred[14] + sred[15];
        if (bid == 0 && tid == 0) {
            float c1 = sred[0] + sred[1] + sred[2] + sred[3]
                     + sred[4] + sred[5] + sred[6] + sred[7];
            g_c[0] = c1; g_c[1] = c2;
        }

        // ---- P table (transposed [j][b]) + per-batch mean ----
        int b = bid;
        float xs = 0.f;
#pragma unroll
        for (int g = 0; g < 4; g++) {
            int j = g * 256 + tid;
            float x = input[b * N + j];
            xs += x;
            g_P[j * BS + b] = make_float2(x, expf(c2 * x));
        }
#pragma unroll
        for (int o = 16; o; o >>= 1) xs += __shfl_xor_sync(0xffffffffu, xs, o);
        __shared__ float sm[8];
        if (lane == 0) sm[w] = xs;
        __syncthreads();
        if (tid == 0) {
            float t = 0.f;
#pragma unroll
            for (int k = 0; k < 8; k++) t += sm[k];
            g_meanx[b] = t * (1.0f / (float)N);
        }
    } else {
        // ---- neighbor compaction for row i, per 256-j segment ----
        int i = bid - BS;
        __shared__ int wbase[32];   // per (seg, warp)
        __shared__ int wcnt[32];
        const int* row = adj + (size_t)i * N;
        unsigned bal[4];
#pragma unroll
        for (int g = 0; g < 4; g++) {        // g == segment
            int j = g * 256 + tid;
            bal[g] = __ballot_sync(0xffffffffu, row[j] > 0);
        }
        if (lane == 0) {
#pragma unroll
            for (int g = 0; g < 4; g++) wcnt[g * 8 + w] = __popc(bal[g]);
        }
        __syncthreads();
        if (tid == 0) {
#pragma unroll
            for (int g = 0; g < 4; g++) {
                int acc = 0;
                for (int o = 0; o < 8; o++) { wbase[g * 8 + o] = acc; acc += wcnt[g * 8 + o]; }
                g_deg[g * N + i] = acc;
            }
        }
        __syncthreads();
#pragma unroll
        for (int g = 0; g < 4; g++) {
            unsigned m = bal[g];
            int rank = __popc(m & ((1u << lane) - 1u));
            int base = wbase[g * 8 + w];
            if ((m >> lane) & 1u)
                g_nbr[(g * N + i) * SEGJ + base + rank] =
                    (unsigned short)(tid & (SEGJ - 1));   // local j within segment
        }
    }
}

// ---------------------------------------------------------------------------
// K2: edge accumulation. Grid 256: seg = bid>>6 (0..3), rowtile = bid&63.
// Block = 512 threads = 16 warps = 16 rows; lane = batch.
// 64KB dyn smem = one 256-j segment of the P table; 2 CTAs/SM -> 32 warps/SM.
// ---------------------------------------------------------------------------
extern __shared__ float2 Ps[];   // SEGJ * BS float2 = 64 KB

__global__ void __launch_bounds__(512, 2) k_edge() {
    int tid  = threadIdx.x;
    int lane = tid & 31;
    int w    = tid >> 5;
    int seg  = blockIdx.x >> 6;
    int rowt = blockIdx.x & 63;
    int i    = rowt * 16 + w;

    // stage segment: 4096 float4, 8 per thread
    {
        float4* dst = reinterpret_cast<float4*>(Ps);
        const float4* src = reinterpret_cast<const float4*>(g_P) + seg * (SEGJ * BS / 2);
#pragma unroll
        for (int t = tid; t < SEGJ * BS / 2; t += 512) dst[t] = src[t];
    }
    __syncthreads();

    float c1 = g_c[0];
    float c2 = g_c[1];
    float t0 = c1 * g_P[i * BS + lane].x;

    int deg = g_deg[seg * N + i];
    const unsigned short* lst = g_nbr + (size_t)(seg * N + i) * SEGJ;

    float sumE = 0.f, sumEx = 0.f;

    int t = 0;
    for (; t + 8 <= deg; t += 8) {
        ushort4 qa = *reinterpret_cast<const ushort4*>(lst + t);
        ushort4 qb = *reinterpret_cast<const ushort4*>(lst + t + 4);
        float2 p0 = Ps[(int)qa.x * BS + lane];
        float2 p1 = Ps[(int)qa.y * BS + lane];
        float2 p2 = Ps[(int)qa.z * BS + lane];
        float2 p3 = Ps[(int)qa.w * BS + lane];
        float2 p4 = Ps[(int)qb.x * BS + lane];
        float2 p5 = Ps[(int)qb.y * BS + lane];
        float2 p6 = Ps[(int)qb.z * BS + lane];
        float2 p7 = Ps[(int)qb.w * BS + lane];
        if (fmaf(c2, p0.x, t0) > 0.f) { sumE += p0.y; sumEx = fmaf(p0.y, p0.x, sumEx); }
        if (fmaf(c2, p1.x, t0) > 0.f) { sumE += p1.y; sumEx = fmaf(p1.y, p1.x, sumEx); }
        if (fmaf(c2, p2.x, t0) > 0.f) { sumE += p2.y; sumEx = fmaf(p2.y, p2.x, sumEx); }
        if (fmaf(c2, p3.x, t0) > 0.f) { sumE += p3.y; sumEx = fmaf(p3.y, p3.x, sumEx); }
        if (fmaf(c2, p4.x, t0) > 0.f) { sumE += p4.y; sumEx = fmaf(p4.y, p4.x, sumEx); }
        if (fmaf(c2, p5.x, t0) > 0.f) { sumE += p5.y; sumEx = fmaf(p5.y, p5.x, sumEx); }
        if (fmaf(c2, p6.x, t0) > 0.f) { sumE += p6.y; sumEx = fmaf(p6.y, p6.x, sumEx); }
        if (fmaf(c2, p7.x, t0) > 0.f) { sumE += p7.y; sumEx = fmaf(p7.y, p7.x, sumEx); }
    }
    for (; t < deg; t++) {
        int idx = lst[t];
        float2 p = Ps[idx * BS + lane];
        if (fmaf(c2, p.x, t0) > 0.f) { sumE += p.y; sumEx = fmaf(p.y, p.x, sumEx); }
    }

    g_part[(size_t)(seg * N + i) * BS + lane] = make_float2(sumE, sumEx);
}

// ---------------------------------------------------------------------------
// K3: epilogue. One warp per row; combine 4 segment partials, compute y,
// write 128 outputs per (b, i) as float4 per lane.
// ---------------------------------------------------------------------------
__device__ __forceinline__ float elu1(float z) {
    return z > 0.0f ? z : (__expf(z) - 1.0f);
}

__global__ void __launch_bounds__(256) k_epi(const float* __restrict__ W,
                                             float* __restrict__ out) {
    int tid  = threadIdx.x;
    int lane = tid & 31;
    int w    = tid >> 5;
    int i    = blockIdx.x * 8 + w;

    float2 a0 = g_part[(size_t)(0 * N + i) * BS + lane];
    float2 a1 = g_part[(size_t)(1 * N + i) * BS + lane];
    float2 a2 = g_part[(size_t)(2 * N + i) * BS + lane];
    float2 a3 = g_part[(size_t)(3 * N + i) * BS + lane];
    float sumE  = (a0.x + a1.x) + (a2.x + a3.x);
    float sumEx = (a0.y + a1.y) + (a2.y + a3.y);

    float y = (sumE > 0.f) ? (sumEx / sumE) : g_meanx[lane];

    float4 wv = *reinterpret_cast<const float4*>(W + lane * 4);
#pragma unroll 1
    for (int b = 0; b < BS; b++) {
        float yb = __shfl_sync(0xffffffffu, y, b);
        float4 o;
        o.x = elu1(yb * wv.x);
        o.y = elu1(yb * wv.y);
        o.z = elu1(yb * wv.z);
        o.w = elu1(yb * wv.w);
        size_t base = ((size_t)b * N + i) * FOUT + lane * 4;
        *reinterpret_cast<float4*>(out + base) = o;
    }
}

// ---------------------------------------------------------------------------
// Launch. Inputs (metadata order): input, adj, ext_input, side_input, W, a
// ---------------------------------------------------------------------------
extern "C" void kernel_launch(void* const* d_in, const int* in_sizes, int n_in,
                              void* d_out, int out_size) {
    const float* input = (const float*)d_in[0];
    const int*   adj   = (const int*)d_in[1];
    const float* W     = (const float*)d_in[4];
    const float* a     = (const float*)d_in[5];
    float* out = (float*)d_out;

    cudaFuncSetAttribute(k_edge, cudaFuncAttributeMaxDynamicSharedMemorySize,
                         SEGJ * BS * (int)sizeof(float2));

    k_pre<<<BS + N, 256>>>(input, adj, W, a);
    k_edge<<<NSEG * 64, 512, SEGJ * BS * sizeof(float2)>>>();
    k_epi<<<N / 8, 256>>>(W, out);
}

// round 17
// speedup vs baseline: 2.2064x; 1.1083x over previous
#include <cuda_runtime.h>
#include <cuda_bf16.h>
#include <cstdint>

#define BS    32
#define N     1024
#define FOUT  128
#define NSEG  4
#define SEGJ  256          // j per segment

// Device-global scratch (allocation-free rule)
__device__ float  g_c[2];                      // c1 = W·a1, c2 = W·a2
__device__ float  g_meanx[BS];                 // per-batch mean of x
__device__ float2 g_P[N * BS];                 // (x, exp(c2*x)) layout [j][b]
__device__ float2 g_part[NSEG * N * BS];       // per-(seg,row,batch) partial (sumE,sumEx)

// ---------------------------------------------------------------------------
// K1: prep (32 blocks). Per-batch: c1/c2 (redundant per block), transposed
// P table (x, exp(c2*x)), per-batch mean.
// ---------------------------------------------------------------------------
__global__ void __launch_bounds__(256) k_prep(const float* __restrict__ input,
                                              const float* __restrict__ W,
                                              const float* __restrict__ a) {
    int b   = blockIdx.x;
    int tid = threadIdx.x;
    int lane = tid & 31;
    int w = tid >> 5;

    // ---- c1, c2 ----
    __shared__ float sred[16];
    float p1 = 0.f, p2 = 0.f;
    if (tid < FOUT) {
        float wv = W[tid];
        p1 = wv * a[tid];
        p2 = wv * a[FOUT + tid];
    }
#pragma unroll
    for (int o = 16; o; o >>= 1) {
        p1 += __shfl_xor_sync(0xffffffffu, p1, o);
        p2 += __shfl_xor_sync(0xffffffffu, p2, o);
    }
    if (lane == 0) { sred[w] = p1; sred[8 + w] = p2; }
    __syncthreads();
    float c2 = sred[8] + sred[9] + sred[10] + sred[11]
             + sred[12] + sred[13] + sred[14] + sred[15];
    if (b == 0 && tid == 0) {
        float c1 = sred[0] + sred[1] + sred[2] + sred[3]
                 + sred[4] + sred[5] + sred[6] + sred[7];
        g_c[0] = c1; g_c[1] = c2;
    }

    // ---- P table (transposed [j][b]) + per-batch mean ----
    float xs = 0.f;
#pragma unroll
    for (int g = 0; g < 4; g++) {
        int j = g * 256 + tid;
        float x = input[b * N + j];
        xs += x;
        g_P[j * BS + b] = make_float2(x, expf(c2 * x));
    }
#pragma unroll
    for (int o = 16; o; o >>= 1) xs += __shfl_xor_sync(0xffffffffu, xs, o);
    __shared__ float sm[8];
    if (lane == 0) sm[w] = xs;
    __syncthreads();
    if (tid == 0) {
        float t = 0.f;
#pragma unroll
        for (int k = 0; k < 8; k++) t += sm[k];
        g_meanx[b] = t * (1.0f / (float)N);
    }
}

// ---------------------------------------------------------------------------
// K2: edge accumulation with in-warp adjacency compaction.
// Grid 256: seg = bid>>6 (0..3), rowtile = bid&63. Block = 512 thr = 16 warps
// = 16 rows; lane = batch. Dyn smem = 64KB P segment + 8KB per-warp lists.
// Each warp loads its own 1KB adjacency chunk (2x int4/lane) BEFORE the P
// stage (latency hidden), ballots it into a compacted ushort list in smem.
// ---------------------------------------------------------------------------
extern __shared__ float2 Ps[];   // [SEGJ*BS] float2 (64KB), then 16*256 ushort (8KB)

__global__ void __launch_bounds__(512, 2) k_edge(const int* __restrict__ adj) {
    int tid  = threadIdx.x;
    int lane = tid & 31;
    int w    = tid >> 5;
    int seg  = blockIdx.x >> 6;
    int rowt = blockIdx.x & 63;
    int i    = rowt * 16 + w;

    // issue adjacency loads early (registers), then stage P to hide latency
    const int4* rowp = reinterpret_cast<const int4*>(adj + (size_t)i * N + seg * SEGJ);
    int4 v0 = rowp[lane * 2];
    int4 v1 = rowp[lane * 2 + 1];

    // stage P segment: 4096 float4, 8 per thread
    {
        float4* dst = reinterpret_cast<float4*>(Ps);
        const float4* src = reinterpret_cast<const float4*>(g_P) + seg * (SEGJ * BS / 2);
#pragma unroll
        for (int t = tid; t < SEGJ * BS / 2; t += 512) dst[t] = src[t];
    }
    __syncthreads();

    // in-warp compaction: 8 ballots -> per-warp ushort list in smem
    unsigned short* lst = reinterpret_cast<unsigned short*>(Ps + SEGJ * BS) + w * SEGJ;
    int vals[8] = { v0.x, v0.y, v0.z, v0.w, v1.x, v1.y, v1.z, v1.w };
    int jb = lane * 8;
    int cnt = 0;
    unsigned ltmask = (1u << lane) - 1u;
#pragma unroll
    for (int k = 0; k < 8; k++) {
        unsigned m = __ballot_sync(0xffffffffu, vals[k] > 0);
        int rnk = __popc(m & ltmask);
        if ((m >> lane) & 1u) lst[cnt + rnk] = (unsigned short)(jb + k);
        cnt += __popc(m);
    }
    __syncwarp();
    int deg = cnt;   // ballot-accumulated: identical across the warp

    float c1 = g_c[0];
    float c2 = g_c[1];
    float t0 = c1 * g_P[i * BS + lane].x;

    float sumE = 0.f, sumEx = 0.f;

    int t = 0;
    for (; t + 8 <= deg; t += 8) {
        ushort4 qa = *reinterpret_cast<const ushort4*>(lst + t);
        ushort4 qb = *reinterpret_cast<const ushort4*>(lst + t + 4);
        float2 p0 = Ps[(int)qa.x * BS + lane];
        float2 p1 = Ps[(int)qa.y * BS + lane];
        float2 p2 = Ps[(int)qa.z * BS + lane];
        float2 p3 = Ps[(int)qa.w * BS + lane];
        float2 p4 = Ps[(int)qb.x * BS + lane];
        float2 p5 = Ps[(int)qb.y * BS + lane];
        float2 p6 = Ps[(int)qb.z * BS + lane];
        float2 p7 = Ps[(int)qb.w * BS + lane];
        if (fmaf(c2, p0.x, t0) > 0.f) { sumE += p0.y; sumEx = fmaf(p0.y, p0.x, sumEx); }
        if (fmaf(c2, p1.x, t0) > 0.f) { sumE += p1.y; sumEx = fmaf(p1.y, p1.x, sumEx); }
        if (fmaf(c2, p2.x, t0) > 0.f) { sumE += p2.y; sumEx = fmaf(p2.y, p2.x, sumEx); }
        if (fmaf(c2, p3.x, t0) > 0.f) { sumE += p3.y; sumEx = fmaf(p3.y, p3.x, sumEx); }
        if (fmaf(c2, p4.x, t0) > 0.f) { sumE += p4.y; sumEx = fmaf(p4.y, p4.x, sumEx); }
        if (fmaf(c2, p5.x, t0) > 0.f) { sumE += p5.y; sumEx = fmaf(p5.y, p5.x, sumEx); }
        if (fmaf(c2, p6.x, t0) > 0.f) { sumE += p6.y; sumEx = fmaf(p6.y, p6.x, sumEx); }
        if (fmaf(c2, p7.x, t0) > 0.f) { sumE += p7.y; sumEx = fmaf(p7.y, p7.x, sumEx); }
    }
    for (; t < deg; t++) {
        int idx = lst[t];
        float2 p = Ps[idx * BS + lane];
        if (fmaf(c2, p.x, t0) > 0.f) { sumE += p.y; sumEx = fmaf(p.y, p.x, sumEx); }
    }

    g_part[(size_t)(seg * N + i) * BS + lane] = make_float2(sumE, sumEx);
}

// ---------------------------------------------------------------------------
// K3: epilogue. One warp per row; combine 4 segment partials, compute y,
// write 128 outputs per (b, i) as float4 per lane.
// ---------------------------------------------------------------------------
__device__ __forceinline__ float elu1(float z) {
    return z > 0.0f ? z : (__expf(z) - 1.0f);
}

__global__ void __launch_bounds__(256) k_epi(const float* __restrict__ W,
                                             float* __restrict__ out) {
    int tid  = threadIdx.x;
    int lane = tid & 31;
    int w    = tid >> 5;
    int i    = blockIdx.x * 8 + w;

    float2 a0 = g_part[(size_t)(0 * N + i) * BS + lane];
    float2 a1 = g_part[(size_t)(1 * N + i) * BS + lane];
    float2 a2 = g_part[(size_t)(2 * N + i) * BS + lane];
    float2 a3 = g_part[(size_t)(3 * N + i) * BS + lane];
    float sumE  = (a0.x + a1.x) + (a2.x + a3.x);
    float sumEx = (a0.y + a1.y) + (a2.y + a3.y);

    float y = (sumE > 0.f) ? (sumEx / sumE) : g_meanx[lane];

    float4 wv = *reinterpret_cast<const float4*>(W + lane * 4);
#pragma unroll 1
    for (int b = 0; b < BS; b++) {
        float yb = __shfl_sync(0xffffffffu, y, b);
        float4 o;
        o.x = elu1(yb * wv.x);
        o.y = elu1(yb * wv.y);
        o.z = elu1(yb * wv.z);
        o.w = elu1(yb * wv.w);
        size_t base = ((size_t)b * N + i) * FOUT + lane * 4;
        *reinterpret_cast<float4*>(out + base) = o;
    }
}

// ---------------------------------------------------------------------------
// Launch. Inputs (metadata order): input, adj, ext_input, side_input, W, a
// ---------------------------------------------------------------------------
extern "C" void kernel_launch(void* const* d_in, const int* in_sizes, int n_in,
                              void* d_out, int out_size) {
    const float* input = (const float*)d_in[0];
    const int*   adj   = (const int*)d_in[1];
    const float* W     = (const float*)d_in[4];
    const float* a     = (const float*)d_in[5];
    float* out = (float*)d_out;

    const int smem_bytes = SEGJ * BS * (int)sizeof(float2)      // P segment (64KB)
                         + 16 * SEGJ * (int)sizeof(unsigned short); // lists (8KB)

    cudaFuncSetAttribute(k_edge, cudaFuncAttributeMaxDynamicSharedMemorySize,
                         smem_bytes);

    k_prep<<<BS, 256>>>(input, W, a);
    k_edge<<<NSEG * 64, 512, smem_bytes>>>(adj);
    k_epi<<<N / 8, 256>>>(W, out);
}